// round 15
// baseline (speedup 1.0000x reference)
#include <cuda_runtime.h>
#include <cuda_fp16.h>
#include <math.h>
#include <stdint.h>

#define B_SZ   16384
#define C_CAM  4
#define DBB    2048
#define DH     512
#define MTOT   (B_SZ * C_CAM)

// -------- device-global scratch (no allocations allowed) --------
__device__ __half g_reg16[(size_t)MTOT * DH];
__device__ __half g_t16 [(size_t)MTOT * DBB];
__device__ __half g_xn16[(size_t)MTOT * DH];
__device__ __half g_h16 [(size_t)MTOT * DH];
__device__ __half g_pw16[(size_t)DH * DBB];
__device__ __half g_wg16[(size_t)C_CAM * DH * DH];
__device__ __half g_wv16[(size_t)C_CAM * DH * DH];
__device__ __half g_wo16[(size_t)C_CAM * 36 * DH];

// -------- helpers --------
__device__ __forceinline__ void mma_f16(float d[4], const unsigned a[4], const unsigned b[2]) {
    asm volatile(
        "mma.sync.aligned.m16n8k16.row.col.f32.f16.f16.f32 "
        "{%0,%1,%2,%3}, {%4,%5,%6,%7}, {%8,%9}, {%0,%1,%2,%3};\n"
        : "+f"(d[0]), "+f"(d[1]), "+f"(d[2]), "+f"(d[3])
        : "r"(a[0]), "r"(a[1]), "r"(a[2]), "r"(a[3]), "r"(b[0]), "r"(b[1]));
}
__device__ __forceinline__ void ldsm4(unsigned r[4], unsigned saddr) {
    asm volatile("ldmatrix.sync.aligned.m8n8.x4.shared.b16 {%0,%1,%2,%3}, [%4];"
        : "=r"(r[0]), "=r"(r[1]), "=r"(r[2]), "=r"(r[3]) : "r"(saddr));
}
__device__ __forceinline__ void ldsm2(unsigned r[2], unsigned saddr) {
    asm volatile("ldmatrix.sync.aligned.m8n8.x2.shared.b16 {%0,%1}, [%2];"
        : "=r"(r[0]), "=r"(r[1]) : "r"(saddr));
}
__device__ __forceinline__ void cp16(void* s, const void* g) {
    unsigned a = (unsigned)__cvta_generic_to_shared(s);
    asm volatile("cp.async.cg.shared.global [%0], [%1], 16;\n" :: "r"(a), "l"(g));
}
__device__ __forceinline__ void cp_commit() { asm volatile("cp.async.commit_group;\n" ::: "memory"); }
__device__ __forceinline__ void cp_wait1()  { asm volatile("cp.async.wait_group 1;\n" ::: "memory"); }
__device__ __forceinline__ void cp_wait0()  { asm volatile("cp.async.wait_group 0;\n" ::: "memory"); }

#define LDSU 36   // uints per smem row: 32 data (=64 halves) + 4 pad

// lane-address offsets (uint units) for ldmatrix fragments
#define A_LANE_OFF(lane) (((lane) & 15) * LDSU + (((lane) >> 4) << 2))
#define B_LANE_OFF(lane) ((((lane) & 7) + (((lane) >> 4) << 3)) * LDSU + ((((lane) >> 3) & 1) << 2))
#define B2_LANE_OFF(lane) (((lane) & 7) * LDSU + ((((lane) >> 3) & 1) << 2))

// =====================================================================
// Stage 0 (fused): thumbnails (16 elem/thread) + all weights fp32->fp16
// blocks [0, 32768): thumbnails; [32768, 36864): pw/wg/wv; [36864, 37152): wo
// =====================================================================
__global__ __launch_bounds__(256) void conv_all(
    const float* __restrict__ T,  const float* __restrict__ pw,
    const float* __restrict__ wg, const float* __restrict__ wv,
    const float* __restrict__ wo)
{
    int bi = blockIdx.x;
    if (bi < 32768) {
        size_t t = (size_t)bi * 256 + threadIdx.x;
        const float4* s4 = (const float4*)T;
        uint4* d4 = (uint4*)g_t16;
        #pragma unroll
        for (int h = 0; h < 2; h++) {
            float4 a = s4[4 * t + 2 * h], b = s4[4 * t + 2 * h + 1];
            __half2 h0 = __floats2half2_rn(a.x, a.y);
            __half2 h1 = __floats2half2_rn(a.z, a.w);
            __half2 h2 = __floats2half2_rn(b.x, b.y);
            __half2 h3 = __floats2half2_rn(b.z, b.w);
            uint4 o;
            o.x = *(unsigned*)&h0; o.y = *(unsigned*)&h1;
            o.z = *(unsigned*)&h2; o.w = *(unsigned*)&h3;
            d4[2 * t + h] = o;
        }
    } else if (bi < 36864) {
        int i = (bi - 32768) * 256 + threadIdx.x;
        g_pw16[i] = __float2half_rn(pw[i]);
        g_wg16[i] = __float2half_rn(wg[i]);
        g_wv16[i] = __float2half_rn(wv[i]);
    } else {
        int i = (bi - 36864) * 256 + threadIdx.x;
        g_wo16[i] = __float2half_rn(wo[i]);
    }
}

// =====================================================================
// Stage 1: reg16 = t16 @ pw16^T + bias.  BM=128, BN=128, BK=64h.
// 3-stage cp.async, 1 barrier/tile, ldmatrix. 256 threads, 2 CTAs/SM.
// Output stored as fp16 (half2).
// =====================================================================
__global__ __launch_bounds__(256, 2) void gemm1_kernel(const float* __restrict__ bias)
{
    extern __shared__ __align__(16) unsigned smb1[];
    unsigned* As = smb1;                    // [3][128*LDSU]
    unsigned* Bs = smb1 + 3 * 128 * LDSU;   // [3][128*LDSU]

    int tid  = threadIdx.x;
    int bm   = blockIdx.y * 128;
    int bn   = blockIdx.x * 128;
    int warp = tid >> 5, lane = tid & 31;
    int wr = warp >> 2, wc = warp & 3;
    int wm = wr * 64,  wn = wc * 32;
    int g = lane >> 2, t = lane & 3;

    float acc[4][4][4];
    #pragma unroll
    for (int i = 0; i < 4; i++)
        #pragma unroll
        for (int j = 0; j < 4; j++)
            #pragma unroll
            for (int k = 0; k < 4; k++) acc[i][j][k] = 0.f;

    int lrow = tid >> 3;
    int lcu  = (tid & 7) * 4;
    int lch  = (tid & 7) * 8;
    const int NK = DBB / 64;        // 32

    const unsigned sAs = (unsigned)__cvta_generic_to_shared(As);
    const unsigned sBs = (unsigned)__cvta_generic_to_shared(Bs);
    const unsigned aLane = sAs + 4u * (unsigned)(wm * LDSU + A_LANE_OFF(lane));
    const unsigned bLane = sBs + 4u * (unsigned)(wn * LDSU + B_LANE_OFF(lane));

    #pragma unroll
    for (int s = 0; s < 2; s++) {
        unsigned* dA = As + s * 128 * LDSU;
        unsigned* dB = Bs + s * 128 * LDSU;
        int k0 = s * 64;
        #pragma unroll
        for (int it = 0; it < 4; it++) {
            int r = lrow + it * 32;
            cp16(&dA[r * LDSU + lcu], g_t16  + (size_t)(bm + r) * DBB + k0 + lch);
            cp16(&dB[r * LDSU + lcu], g_pw16 + (size_t)(bn + r) * DBB + k0 + lch);
        }
        cp_commit();
    }

    int slot = 0, nslot = 2;
    for (int i = 0; i < NK; i++) {
        cp_wait1();
        __syncthreads();

        if (i + 2 < NK) {
            int k0 = (i + 2) * 64;
            unsigned* dA = As + nslot * 128 * LDSU;
            unsigned* dB = Bs + nslot * 128 * LDSU;
            #pragma unroll
            for (int it = 0; it < 4; it++) {
                int r = lrow + it * 32;
                cp16(&dA[r * LDSU + lcu], g_t16  + (size_t)(bm + r) * DBB + k0 + lch);
                cp16(&dB[r * LDSU + lcu], g_pw16 + (size_t)(bn + r) * DBB + k0 + lch);
            }
        }
        cp_commit();

        unsigned aBase = aLane + 4u * (unsigned)(slot * 128 * LDSU);
        unsigned bBase = bLane + 4u * (unsigned)(slot * 128 * LDSU);
        #pragma unroll
        for (int kk = 0; kk < 32; kk += 8) {
            unsigned afr[4][4], b4[2][4];
            #pragma unroll
            for (int mt = 0; mt < 4; mt++)
                ldsm4(afr[mt], aBase + 4u * (unsigned)(mt * 16 * LDSU + kk));
            #pragma unroll
            for (int p = 0; p < 2; p++)
                ldsm4(b4[p], bBase + 4u * (unsigned)(p * 16 * LDSU + kk));
            #pragma unroll
            for (int mt = 0; mt < 4; mt++)
                #pragma unroll
                for (int nt = 0; nt < 4; nt++)
                    mma_f16(acc[mt][nt], afr[mt], &b4[nt >> 1][(nt & 1) * 2]);
        }
        slot = (slot == 2) ? 0 : slot + 1;
        nslot = (nslot == 2) ? 0 : nslot + 1;
    }

    #pragma unroll
    for (int mt = 0; mt < 4; mt++) {
        #pragma unroll
        for (int nt = 0; nt < 4; nt++) {
            int row0 = bm + wm + mt * 16 + g;
            int col  = bn + wn + nt * 8 + t * 2;
            float b0 = bias[col], b1 = bias[col + 1];
            *(__half2*)(g_reg16 + (size_t)row0 * DH + col) =
                __floats2half2_rn(acc[mt][nt][0] + b0, acc[mt][nt][1] + b1);
            *(__half2*)(g_reg16 + (size_t)(row0 + 8) * DH + col) =
                __floats2half2_rn(acc[mt][nt][2] + b0, acc[mt][nt][3] + b1);
        }
    }
}

// =====================================================================
// Stage 2: LayerNorm (warp/row) on fp16 input, fp16 output
// =====================================================================
__global__ __launch_bounds__(256) void ln_kernel(
    const float* __restrict__ gamma, const float* __restrict__ beta)
{
    int wglob = (blockIdx.x * blockDim.x + threadIdx.x) >> 5;
    int lane  = threadIdx.x & 31;
    if (wglob >= MTOT) return;
    int c = wglob & 3;
    const __half2* row2 = (const __half2*)(g_reg16 + (size_t)wglob * DH);
    float2 v[8]; float s = 0.f, s2 = 0.f;
    #pragma unroll
    for (int i = 0; i < 8; i++) {
        v[i] = __half22float2(row2[lane + i * 32]);
        s += v[i].x + v[i].y;
        s2 += v[i].x * v[i].x + v[i].y * v[i].y;
    }
    #pragma unroll
    for (int o = 16; o > 0; o >>= 1) {
        s  += __shfl_xor_sync(0xffffffffu, s,  o);
        s2 += __shfl_xor_sync(0xffffffffu, s2, o);
    }
    float mu   = s * (1.f / DH);
    float var  = s2 * (1.f / DH) - mu * mu;
    float rstd = rsqrtf(var + 1e-5f);
    __half2* orow = (__half2*)(g_xn16 + (size_t)wglob * DH);
    const float2* ga2 = (const float2*)(gamma + c * DH);
    const float2* be2 = (const float2*)(beta  + c * DH);
    #pragma unroll
    for (int i = 0; i < 8; i++) {
        int idx = lane + i * 32;
        float2 ga = ga2[idx], be = be2[idx];
        float x0 = (v[i].x - mu) * rstd * ga.x + be.x;
        float x1 = (v[i].y - mu) * rstd * ga.y + be.y;
        orow[idx] = __floats2half2_rn(x0, x1);
    }
}

// =====================================================================
// Stage 3: per-camera dual GEMM + SwiGLU. BM=128, BN=64, BK=64h. NK=8.
// 3-stage, 1 barrier/tile, ldmatrix loads.
// =====================================================================
__global__ __launch_bounds__(256, 2) void gemm2_kernel()
{
    extern __shared__ __align__(16) unsigned smb2[];
    unsigned* As  = smb2;                       // [3][128*LDSU]
    unsigned* Bgs = smb2 + 3 * 128 * LDSU;      // [3][64*LDSU]
    unsigned* Bvs = Bgs + 3 * 64 * LDSU;        // [3][64*LDSU]

    int tid  = threadIdx.x;
    int bm   = blockIdx.y * 128;
    int bn   = blockIdx.x * 64;
    int c    = blockIdx.z;
    int warp = tid >> 5, lane = tid & 31;
    int wr = warp >> 1, wc = warp & 1;
    int wm = wr * 32,  wn = wc * 32;
    int g = lane >> 2, t = lane & 3;

    float accg[2][4][4], accv[2][4][4];
    #pragma unroll
    for (int i = 0; i < 2; i++)
        #pragma unroll
        for (int j = 0; j < 4; j++)
            #pragma unroll
            for (int k = 0; k < 4; k++) { accg[i][j][k] = 0.f; accv[i][j][k] = 0.f; }

    int lrow = tid >> 3;
    int lcu  = (tid & 7) * 4;
    int lch  = (tid & 7) * 8;
    const __half* wg0 = g_wg16 + (size_t)c * DH * DH;
    const __half* wv0 = g_wv16 + (size_t)c * DH * DH;
    const int NK = DH / 64;   // 8

    const unsigned sAs = (unsigned)__cvta_generic_to_shared(As);
    const unsigned sGs = (unsigned)__cvta_generic_to_shared(Bgs);
    const unsigned sVs = (unsigned)__cvta_generic_to_shared(Bvs);
    const unsigned aLane = sAs + 4u * (unsigned)(wm * LDSU + A_LANE_OFF(lane));
    const unsigned gLane = sGs + 4u * (unsigned)(wn * LDSU + B_LANE_OFF(lane));
    const unsigned vLane = sVs + 4u * (unsigned)(wn * LDSU + B_LANE_OFF(lane));

    #pragma unroll
    for (int s = 0; s < 2; s++) {
        int k0 = s * 64;
        unsigned* dA = As  + s * 128 * LDSU;
        unsigned* dG = Bgs + s * 64 * LDSU;
        unsigned* dV = Bvs + s * 64 * LDSU;
        #pragma unroll
        for (int it = 0; it < 4; it++) {
            int r = lrow + it * 32;
            cp16(&dA[r * LDSU + lcu], g_xn16 + ((size_t)(bm + r) * 4 + c) * DH + k0 + lch);
        }
        #pragma unroll
        for (int it = 0; it < 2; it++) {
            int r = lrow + it * 32;
            cp16(&dG[r * LDSU + lcu], wg0 + (size_t)(bn + r) * DH + k0 + lch);
            cp16(&dV[r * LDSU + lcu], wv0 + (size_t)(bn + r) * DH + k0 + lch);
        }
        cp_commit();
    }

    int slot = 0, nslot = 2;
    for (int i = 0; i < NK; i++) {
        cp_wait1();
        __syncthreads();

        if (i + 2 < NK) {
            int k0 = (i + 2) * 64;
            unsigned* dA = As  + nslot * 128 * LDSU;
            unsigned* dG = Bgs + nslot * 64 * LDSU;
            unsigned* dV = Bvs + nslot * 64 * LDSU;
            #pragma unroll
            for (int it = 0; it < 4; it++) {
                int r = lrow + it * 32;
                cp16(&dA[r * LDSU + lcu], g_xn16 + ((size_t)(bm + r) * 4 + c) * DH + k0 + lch);
            }
            #pragma unroll
            for (int it = 0; it < 2; it++) {
                int r = lrow + it * 32;
                cp16(&dG[r * LDSU + lcu], wg0 + (size_t)(bn + r) * DH + k0 + lch);
                cp16(&dV[r * LDSU + lcu], wv0 + (size_t)(bn + r) * DH + k0 + lch);
            }
        }
        cp_commit();

        unsigned aBase = aLane + 4u * (unsigned)(slot * 128 * LDSU);
        unsigned gBase = gLane + 4u * (unsigned)(slot * 64 * LDSU);
        unsigned vBase = vLane + 4u * (unsigned)(slot * 64 * LDSU);
        #pragma unroll
        for (int kk = 0; kk < 32; kk += 8) {
            unsigned afr[2][4], g4[2][4], v4[2][4];
            #pragma unroll
            for (int mt = 0; mt < 2; mt++)
                ldsm4(afr[mt], aBase + 4u * (unsigned)(mt * 16 * LDSU + kk));
            #pragma unroll
            for (int p = 0; p < 2; p++) {
                ldsm4(g4[p], gBase + 4u * (unsigned)(p * 16 * LDSU + kk));
                ldsm4(v4[p], vBase + 4u * (unsigned)(p * 16 * LDSU + kk));
            }
            #pragma unroll
            for (int mt = 0; mt < 2; mt++)
                #pragma unroll
                for (int nt = 0; nt < 4; nt++) {
                    mma_f16(accg[mt][nt], afr[mt], &g4[nt >> 1][(nt & 1) * 2]);
                    mma_f16(accv[mt][nt], afr[mt], &v4[nt >> 1][(nt & 1) * 2]);
                }
        }
        slot = (slot == 2) ? 0 : slot + 1;
        nslot = (nslot == 2) ? 0 : nslot + 1;
    }

    #pragma unroll
    for (int mt = 0; mt < 2; mt++) {
        #pragma unroll
        for (int nt = 0; nt < 4; nt++) {
            int row0 = bm + wm + mt * 16 + g;
            int col  = bn + wn + nt * 8 + t * 2;
            #pragma unroll
            for (int half = 0; half < 2; half++) {
                int rr = row0 + half * 8;
                float gte0 = accg[mt][nt][half * 2 + 0];
                float gte1 = accg[mt][nt][half * 2 + 1];
                float val0 = accv[mt][nt][half * 2 + 0];
                float val1 = accv[mt][nt][half * 2 + 1];
                float h0 = gte0 / (1.f + expf(-gte0)) * val0;
                float h1 = gte1 / (1.f + expf(-gte1)) * val1;
                __half2* dst = (__half2*)(g_h16 + ((size_t)rr * 4 + c) * DH + col);
                *dst = __floats2half2_rn(h0, h1);
            }
        }
    }
}

// =====================================================================
// Stage 4 (FUSED): per-camera A = h16 @ wo16^T, then skew + clip + expm
// in-CTA via smem staging; writes out[C,B,6,6] directly.
// =====================================================================
__global__ __launch_bounds__(256, 2) void gemm3_kernel(float* __restrict__ out)
{
    extern __shared__ __align__(16) unsigned smb3[];
    unsigned* As = smb3;                     // [2][128*LDSU]
    unsigned* Bs = smb3 + 2 * 128 * LDSU;    // [2][40*LDSU]

    int tid  = threadIdx.x;
    int bm   = blockIdx.y * 128;
    int c    = blockIdx.z;
    int warp = tid >> 5, lane = tid & 31;
    int wm   = warp * 16;
    int g = lane >> 2, t = lane & 3;

    for (int i = tid; i < 2 * 4 * LDSU; i += 256) {
        int b = i / (4 * LDSU);
        int rem = i % (4 * LDSU);
        Bs[b * 40 * LDSU + 36 * LDSU + rem] = 0u;
    }

    float acc[5][4];
    #pragma unroll
    for (int j = 0; j < 5; j++)
        #pragma unroll
        for (int k = 0; k < 4; k++) acc[j][k] = 0.f;

    int lrow = tid >> 3;
    int lcu  = (tid & 7) * 4;
    int lch  = (tid & 7) * 8;
    const __half* wo0 = g_wo16 + (size_t)c * 36 * DH;
    const int NK = DH / 64;   // 8

    const unsigned sAs = (unsigned)__cvta_generic_to_shared(As);
    const unsigned sBs = (unsigned)__cvta_generic_to_shared(Bs);
    const unsigned aLane  = sAs + 4u * (unsigned)(wm * LDSU + A_LANE_OFF(lane));
    const unsigned bLane  = sBs + 4u * (unsigned)(B_LANE_OFF(lane));
    const unsigned b2Lane = sBs + 4u * (unsigned)(32 * LDSU + B2_LANE_OFF(lane));

    {
        #pragma unroll
        for (int it = 0; it < 4; it++) {
            int r = lrow + it * 32;
            cp16(&As[r * LDSU + lcu], g_h16 + ((size_t)(bm + r) * 4 + c) * DH + lch);
        }
        for (int i2 = tid; i2 < 288; i2 += 256) {
            int r = i2 >> 3, cu = (i2 & 7) * 4;
            cp16(&Bs[r * LDSU + cu], wo0 + (size_t)r * DH + (i2 & 7) * 8);
        }
        cp_commit();
    }

    for (int i = 0; i < NK; i++) {
        if (i + 1 < NK) {
            int k0 = (i + 1) * 64;
            int b = (i + 1) & 1;
            unsigned* dA = As + b * 128 * LDSU;
            unsigned* dB = Bs + b * 40 * LDSU;
            #pragma unroll
            for (int it = 0; it < 4; it++) {
                int r = lrow + it * 32;
                cp16(&dA[r * LDSU + lcu], g_h16 + ((size_t)(bm + r) * 4 + c) * DH + k0 + lch);
            }
            for (int i2 = tid; i2 < 288; i2 += 256) {
                int r = i2 >> 3, cu = (i2 & 7) * 4;
                cp16(&dB[r * LDSU + cu], wo0 + (size_t)r * DH + k0 + (i2 & 7) * 8);
            }
            cp_commit(); cp_wait1();
        } else {
            cp_wait0();
        }
        __syncthreads();

        int b = i & 1;
        unsigned aBase = aLane  + 4u * (unsigned)(b * 128 * LDSU);
        unsigned bBase = bLane  + 4u * (unsigned)(b * 40 * LDSU);
        unsigned cBase = b2Lane + 4u * (unsigned)(b * 40 * LDSU);
        #pragma unroll
        for (int kk = 0; kk < 32; kk += 8) {
            unsigned afr[4], b4[2][4], b2[2];
            ldsm4(afr, aBase + 4u * (unsigned)kk);
            #pragma unroll
            for (int p = 0; p < 2; p++)
                ldsm4(b4[p], bBase + 4u * (unsigned)(p * 16 * LDSU + kk));
            ldsm2(b2, cBase + 4u * (unsigned)kk);
            #pragma unroll
            for (int nt = 0; nt < 4; nt++)
                mma_f16(acc[nt], afr, &b4[nt >> 1][(nt & 1) * 2]);
            mma_f16(acc[4], afr, b2);
        }
        __syncthreads();
    }

    // ---- stage accumulators into smem (reuse pipeline buffers) ----
    float* stage = (float*)smb3;   // 128 x 37 floats = 18944 B
    #pragma unroll
    for (int nt = 0; nt < 5; nt++) {
        int col = nt * 8 + t * 2;
        if (col < 36) {
            int lr = wm + g;
            stage[lr * 37 + col]           = acc[nt][0];
            stage[lr * 37 + col + 1]       = acc[nt][1];
            stage[(lr + 8) * 37 + col]     = acc[nt][2];
            stage[(lr + 8) * 37 + col + 1] = acc[nt][3];
        }
    }
    __syncthreads();

    // ---- fused skew + clip + expm: one thread per matrix ----
    if (tid < 128) {
        const float* raw = stage + tid * 37;
        float A[36]; float ss = 0.f;
        #pragma unroll
        for (int i = 0; i < 6; i++)
            #pragma unroll
            for (int j = 0; j < 6; j++) {
                float v = raw[i * 6 + j] - raw[j * 6 + i];
                A[i * 6 + j] = v; ss += v * v;
            }
        float frob  = sqrtf(ss);
        float scale = fminf(frob, 3.0f) / fmaxf(frob, 1e-8f);

        float Asm[36];
        #pragma unroll
        for (int i = 0; i < 36; i++) Asm[i] = A[i] * scale * 0.0625f;

        float E[36], term[36];
        #pragma unroll
        for (int i = 0; i < 36; i++) { E[i] = (i % 7 == 0) ? 1.f : 0.f; term[i] = E[i]; }

        #pragma unroll 1
        for (int k = 1; k <= 12; k++) {
            float nt2[36];
            float inv = 1.f / (float)k;
            #pragma unroll
            for (int i = 0; i < 6; i++)
                #pragma unroll
                for (int j = 0; j < 6; j++) {
                    float sacc = 0.f;
                    #pragma unroll
                    for (int l = 0; l < 6; l++) sacc += term[i * 6 + l] * Asm[l * 6 + j];
                    nt2[i * 6 + j] = sacc * inv;
                }
            #pragma unroll
            for (int i = 0; i < 36; i++) { term[i] = nt2[i]; E[i] += nt2[i]; }
        }
        #pragma unroll 1
        for (int s = 0; s < 4; s++) {
            float nt2[36];
            #pragma unroll
            for (int i = 0; i < 6; i++)
                #pragma unroll
                for (int j = 0; j < 6; j++) {
                    float sacc = 0.f;
                    #pragma unroll
                    for (int l = 0; l < 6; l++) sacc += E[i * 6 + l] * E[l * 6 + j];
                    nt2[i * 6 + j] = sacc;
                }
            #pragma unroll
            for (int i = 0; i < 36; i++) E[i] = nt2[i];
        }

        float* dst = out + ((size_t)c * B_SZ + (bm + tid)) * 36;
        #pragma unroll
        for (int i = 0; i < 36; i++) dst[i] = E[i];
    }
}

// =====================================================================
extern "C" void kernel_launch(void* const* d_in, const int* in_sizes, int n_in,
                              void* d_out, int out_size)
{
    const float* thumb  = (const float*)d_in[0];
    const float* proj_w = (const float*)d_in[1];
    const float* proj_b = (const float*)d_in[2];
    const float* gamma  = (const float*)d_in[3];
    const float* beta   = (const float*)d_in[4];
    const float* w_gate = (const float*)d_in[5];
    const float* w_val  = (const float*)d_in[6];
    const float* w_out  = (const float*)d_in[7];
    float* out = (float*)d_out;

    (void)in_sizes; (void)n_in; (void)out_size;

    const int SM1 = 3 * 2 * 128 * LDSU * 4;                 // 110592
    const int SM2 = (3 * 128 * LDSU + 6 * 64 * LDSU) * 4;   // 110592
    const int SM3 = (2 * 128 * LDSU + 2 * 40 * LDSU) * 4;   // 48384

    cudaFuncSetAttribute(gemm1_kernel, cudaFuncAttributeMaxDynamicSharedMemorySize, SM1);
    cudaFuncSetAttribute(gemm2_kernel, cudaFuncAttributeMaxDynamicSharedMemorySize, SM2);
    cudaFuncSetAttribute(gemm3_kernel, cudaFuncAttributeMaxDynamicSharedMemorySize, SM3);

    conv_all<<<37152, 256>>>(thumb, proj_w, w_gate, w_val, w_out);
    gemm1_kernel<<<dim3(4, 512), 256, SM1>>>(proj_b);
    ln_kernel<<<MTOT / 8, 256>>>(gamma, beta);
    gemm2_kernel<<<dim3(8, 128, 4), 256, SM2>>>();
    gemm3_kernel<<<dim3(1, 128, 4), 256, SM3>>>(out);
}

// round 16
// speedup vs baseline: 1.4788x; 1.4788x over previous
#include <cuda_runtime.h>
#include <cuda_fp16.h>
#include <math.h>
#include <stdint.h>

#define B_SZ   16384
#define C_CAM  4
#define DBB    2048
#define DH     512
#define MTOT   (B_SZ * C_CAM)

// -------- device-global scratch (no allocations allowed) --------
__device__ __half g_reg16[(size_t)MTOT * DH];
__device__ __half g_t16 [(size_t)MTOT * DBB];
__device__ __half g_xn16[(size_t)MTOT * DH];
__device__ __half g_h16 [(size_t)MTOT * DH];
__device__ __half g_pw16[(size_t)DH * DBB];
__device__ __half g_wg16[(size_t)C_CAM * DH * DH];
__device__ __half g_wv16[(size_t)C_CAM * DH * DH];
__device__ __half g_wo16[(size_t)C_CAM * 36 * DH];

// -------- helpers --------
__device__ __forceinline__ void mma_f16(float d[4], const unsigned a[4], const unsigned b[2]) {
    asm volatile(
        "mma.sync.aligned.m16n8k16.row.col.f32.f16.f16.f32 "
        "{%0,%1,%2,%3}, {%4,%5,%6,%7}, {%8,%9}, {%0,%1,%2,%3};\n"
        : "+f"(d[0]), "+f"(d[1]), "+f"(d[2]), "+f"(d[3])
        : "r"(a[0]), "r"(a[1]), "r"(a[2]), "r"(a[3]), "r"(b[0]), "r"(b[1]));
}
__device__ __forceinline__ void ldsm4(unsigned r[4], unsigned saddr) {
    asm volatile("ldmatrix.sync.aligned.m8n8.x4.shared.b16 {%0,%1,%2,%3}, [%4];"
        : "=r"(r[0]), "=r"(r[1]), "=r"(r[2]), "=r"(r[3]) : "r"(saddr));
}
__device__ __forceinline__ void ldsm2(unsigned r[2], unsigned saddr) {
    asm volatile("ldmatrix.sync.aligned.m8n8.x2.shared.b16 {%0,%1}, [%2];"
        : "=r"(r[0]), "=r"(r[1]) : "r"(saddr));
}
__device__ __forceinline__ void cp16(void* s, const void* g) {
    unsigned a = (unsigned)__cvta_generic_to_shared(s);
    asm volatile("cp.async.cg.shared.global [%0], [%1], 16;\n" :: "r"(a), "l"(g));
}
__device__ __forceinline__ void cp_commit() { asm volatile("cp.async.commit_group;\n" ::: "memory"); }
__device__ __forceinline__ void cp_wait1()  { asm volatile("cp.async.wait_group 1;\n" ::: "memory"); }
__device__ __forceinline__ void cp_wait0()  { asm volatile("cp.async.wait_group 0;\n" ::: "memory"); }

#define LDSU 36   // uints per smem row: 32 data (=64 halves) + 4 pad

// lane-address offsets (uint units) for ldmatrix fragments
#define A_LANE_OFF(lane) (((lane) & 15) * LDSU + (((lane) >> 4) << 2))
#define B_LANE_OFF(lane) ((((lane) & 7) + (((lane) >> 4) << 3)) * LDSU + ((((lane) >> 3) & 1) << 2))
#define B2_LANE_OFF(lane) (((lane) & 7) * LDSU + ((((lane) >> 3) & 1) << 2))

// =====================================================================
// Stage 0 (fused): thumbnails (16 elem/thread) + all weights fp32->fp16
// blocks [0, 32768): thumbnails; [32768, 36864): pw/wg/wv; [36864, 37152): wo
// =====================================================================
__global__ __launch_bounds__(256) void conv_all(
    const float* __restrict__ T,  const float* __restrict__ pw,
    const float* __restrict__ wg, const float* __restrict__ wv,
    const float* __restrict__ wo)
{
    int bi = blockIdx.x;
    if (bi < 32768) {
        size_t t = (size_t)bi * 256 + threadIdx.x;
        const float4* s4 = (const float4*)T;
        uint4* d4 = (uint4*)g_t16;
        #pragma unroll
        for (int h = 0; h < 2; h++) {
            float4 a = s4[4 * t + 2 * h], b = s4[4 * t + 2 * h + 1];
            __half2 h0 = __floats2half2_rn(a.x, a.y);
            __half2 h1 = __floats2half2_rn(a.z, a.w);
            __half2 h2 = __floats2half2_rn(b.x, b.y);
            __half2 h3 = __floats2half2_rn(b.z, b.w);
            uint4 o;
            o.x = *(unsigned*)&h0; o.y = *(unsigned*)&h1;
            o.z = *(unsigned*)&h2; o.w = *(unsigned*)&h3;
            d4[2 * t + h] = o;
        }
    } else if (bi < 36864) {
        int i = (bi - 32768) * 256 + threadIdx.x;
        g_pw16[i] = __float2half_rn(pw[i]);
        g_wg16[i] = __float2half_rn(wg[i]);
        g_wv16[i] = __float2half_rn(wv[i]);
    } else {
        int i = (bi - 36864) * 256 + threadIdx.x;
        g_wo16[i] = __float2half_rn(wo[i]);
    }
}

// =====================================================================
// Stage 1: reg16 = t16 @ pw16^T + bias.  BM=128, BN=128, BK=64h.
// 3-stage cp.async, 1 barrier/tile, ldmatrix. 256 threads, 2 CTAs/SM.
// Output stored as fp16 (half2).
// =====================================================================
__global__ __launch_bounds__(256, 2) void gemm1_kernel(const float* __restrict__ bias)
{
    extern __shared__ __align__(16) unsigned smb1[];
    unsigned* As = smb1;                    // [3][128*LDSU]
    unsigned* Bs = smb1 + 3 * 128 * LDSU;   // [3][128*LDSU]

    int tid  = threadIdx.x;
    int bm   = blockIdx.y * 128;
    int bn   = blockIdx.x * 128;
    int warp = tid >> 5, lane = tid & 31;
    int wr = warp >> 2, wc = warp & 3;
    int wm = wr * 64,  wn = wc * 32;
    int g = lane >> 2, t = lane & 3;

    float acc[4][4][4];
    #pragma unroll
    for (int i = 0; i < 4; i++)
        #pragma unroll
        for (int j = 0; j < 4; j++)
            #pragma unroll
            for (int k = 0; k < 4; k++) acc[i][j][k] = 0.f;

    int lrow = tid >> 3;
    int lcu  = (tid & 7) * 4;
    int lch  = (tid & 7) * 8;
    const int NK = DBB / 64;        // 32

    const unsigned sAs = (unsigned)__cvta_generic_to_shared(As);
    const unsigned sBs = (unsigned)__cvta_generic_to_shared(Bs);
    const unsigned aLane = sAs + 4u * (unsigned)(wm * LDSU + A_LANE_OFF(lane));
    const unsigned bLane = sBs + 4u * (unsigned)(wn * LDSU + B_LANE_OFF(lane));

    #pragma unroll
    for (int s = 0; s < 2; s++) {
        unsigned* dA = As + s * 128 * LDSU;
        unsigned* dB = Bs + s * 128 * LDSU;
        int k0 = s * 64;
        #pragma unroll
        for (int it = 0; it < 4; it++) {
            int r = lrow + it * 32;
            cp16(&dA[r * LDSU + lcu], g_t16  + (size_t)(bm + r) * DBB + k0 + lch);
            cp16(&dB[r * LDSU + lcu], g_pw16 + (size_t)(bn + r) * DBB + k0 + lch);
        }
        cp_commit();
    }

    int slot = 0, nslot = 2;
    for (int i = 0; i < NK; i++) {
        cp_wait1();
        __syncthreads();

        if (i + 2 < NK) {
            int k0 = (i + 2) * 64;
            unsigned* dA = As + nslot * 128 * LDSU;
            unsigned* dB = Bs + nslot * 128 * LDSU;
            #pragma unroll
            for (int it = 0; it < 4; it++) {
                int r = lrow + it * 32;
                cp16(&dA[r * LDSU + lcu], g_t16  + (size_t)(bm + r) * DBB + k0 + lch);
                cp16(&dB[r * LDSU + lcu], g_pw16 + (size_t)(bn + r) * DBB + k0 + lch);
            }
        }
        cp_commit();

        unsigned aBase = aLane + 4u * (unsigned)(slot * 128 * LDSU);
        unsigned bBase = bLane + 4u * (unsigned)(slot * 128 * LDSU);
        #pragma unroll
        for (int kk = 0; kk < 32; kk += 8) {
            unsigned afr[4][4], b4[2][4];
            #pragma unroll
            for (int mt = 0; mt < 4; mt++)
                ldsm4(afr[mt], aBase + 4u * (unsigned)(mt * 16 * LDSU + kk));
            #pragma unroll
            for (int p = 0; p < 2; p++)
                ldsm4(b4[p], bBase + 4u * (unsigned)(p * 16 * LDSU + kk));
            #pragma unroll
            for (int mt = 0; mt < 4; mt++)
                #pragma unroll
                for (int nt = 0; nt < 4; nt++)
                    mma_f16(acc[mt][nt], afr[mt], &b4[nt >> 1][(nt & 1) * 2]);
        }
        slot = (slot == 2) ? 0 : slot + 1;
        nslot = (nslot == 2) ? 0 : nslot + 1;
    }

    #pragma unroll
    for (int mt = 0; mt < 4; mt++) {
        #pragma unroll
        for (int nt = 0; nt < 4; nt++) {
            int row0 = bm + wm + mt * 16 + g;
            int col  = bn + wn + nt * 8 + t * 2;
            float b0 = bias[col], b1 = bias[col + 1];
            *(__half2*)(g_reg16 + (size_t)row0 * DH + col) =
                __floats2half2_rn(acc[mt][nt][0] + b0, acc[mt][nt][1] + b1);
            *(__half2*)(g_reg16 + (size_t)(row0 + 8) * DH + col) =
                __floats2half2_rn(acc[mt][nt][2] + b0, acc[mt][nt][3] + b1);
        }
    }
}

// =====================================================================
// Stage 2: LayerNorm (warp/row) on fp16 input, fp16 output
// =====================================================================
__global__ __launch_bounds__(256) void ln_kernel(
    const float* __restrict__ gamma, const float* __restrict__ beta)
{
    int wglob = (blockIdx.x * blockDim.x + threadIdx.x) >> 5;
    int lane  = threadIdx.x & 31;
    if (wglob >= MTOT) return;
    int c = wglob & 3;
    const __half2* row2 = (const __half2*)(g_reg16 + (size_t)wglob * DH);
    float2 v[8]; float s = 0.f, s2 = 0.f;
    #pragma unroll
    for (int i = 0; i < 8; i++) {
        v[i] = __half22float2(row2[lane + i * 32]);
        s += v[i].x + v[i].y;
        s2 += v[i].x * v[i].x + v[i].y * v[i].y;
    }
    #pragma unroll
    for (int o = 16; o > 0; o >>= 1) {
        s  += __shfl_xor_sync(0xffffffffu, s,  o);
        s2 += __shfl_xor_sync(0xffffffffu, s2, o);
    }
    float mu   = s * (1.f / DH);
    float var  = s2 * (1.f / DH) - mu * mu;
    float rstd = rsqrtf(var + 1e-5f);
    __half2* orow = (__half2*)(g_xn16 + (size_t)wglob * DH);
    const float2* ga2 = (const float2*)(gamma + c * DH);
    const float2* be2 = (const float2*)(beta  + c * DH);
    #pragma unroll
    for (int i = 0; i < 8; i++) {
        int idx = lane + i * 32;
        float2 ga = ga2[idx], be = be2[idx];
        float x0 = (v[i].x - mu) * rstd * ga.x + be.x;
        float x1 = (v[i].y - mu) * rstd * ga.y + be.y;
        orow[idx] = __floats2half2_rn(x0, x1);
    }
}

// =====================================================================
// Stage 3: per-camera dual GEMM + SwiGLU. BM=128, BN=64, BK=64h. NK=8.
// 3-stage, 1 barrier/tile, ldmatrix loads.
// =====================================================================
__global__ __launch_bounds__(256, 2) void gemm2_kernel()
{
    extern __shared__ __align__(16) unsigned smb2[];
    unsigned* As  = smb2;                       // [3][128*LDSU]
    unsigned* Bgs = smb2 + 3 * 128 * LDSU;      // [3][64*LDSU]
    unsigned* Bvs = Bgs + 3 * 64 * LDSU;        // [3][64*LDSU]

    int tid  = threadIdx.x;
    int bm   = blockIdx.y * 128;
    int bn   = blockIdx.x * 64;
    int c    = blockIdx.z;
    int warp = tid >> 5, lane = tid & 31;
    int wr = warp >> 1, wc = warp & 1;
    int wm = wr * 32,  wn = wc * 32;
    int g = lane >> 2, t = lane & 3;

    float accg[2][4][4], accv[2][4][4];
    #pragma unroll
    for (int i = 0; i < 2; i++)
        #pragma unroll
        for (int j = 0; j < 4; j++)
            #pragma unroll
            for (int k = 0; k < 4; k++) { accg[i][j][k] = 0.f; accv[i][j][k] = 0.f; }

    int lrow = tid >> 3;
    int lcu  = (tid & 7) * 4;
    int lch  = (tid & 7) * 8;
    const __half* wg0 = g_wg16 + (size_t)c * DH * DH;
    const __half* wv0 = g_wv16 + (size_t)c * DH * DH;
    const int NK = DH / 64;   // 8

    const unsigned sAs = (unsigned)__cvta_generic_to_shared(As);
    const unsigned sGs = (unsigned)__cvta_generic_to_shared(Bgs);
    const unsigned sVs = (unsigned)__cvta_generic_to_shared(Bvs);
    const unsigned aLane = sAs + 4u * (unsigned)(wm * LDSU + A_LANE_OFF(lane));
    const unsigned gLane = sGs + 4u * (unsigned)(wn * LDSU + B_LANE_OFF(lane));
    const unsigned vLane = sVs + 4u * (unsigned)(wn * LDSU + B_LANE_OFF(lane));

    #pragma unroll
    for (int s = 0; s < 2; s++) {
        int k0 = s * 64;
        unsigned* dA = As  + s * 128 * LDSU;
        unsigned* dG = Bgs + s * 64 * LDSU;
        unsigned* dV = Bvs + s * 64 * LDSU;
        #pragma unroll
        for (int it = 0; it < 4; it++) {
            int r = lrow + it * 32;
            cp16(&dA[r * LDSU + lcu], g_xn16 + ((size_t)(bm + r) * 4 + c) * DH + k0 + lch);
        }
        #pragma unroll
        for (int it = 0; it < 2; it++) {
            int r = lrow + it * 32;
            cp16(&dG[r * LDSU + lcu], wg0 + (size_t)(bn + r) * DH + k0 + lch);
            cp16(&dV[r * LDSU + lcu], wv0 + (size_t)(bn + r) * DH + k0 + lch);
        }
        cp_commit();
    }

    int slot = 0, nslot = 2;
    for (int i = 0; i < NK; i++) {
        cp_wait1();
        __syncthreads();

        if (i + 2 < NK) {
            int k0 = (i + 2) * 64;
            unsigned* dA = As  + nslot * 128 * LDSU;
            unsigned* dG = Bgs + nslot * 64 * LDSU;
            unsigned* dV = Bvs + nslot * 64 * LDSU;
            #pragma unroll
            for (int it = 0; it < 4; it++) {
                int r = lrow + it * 32;
                cp16(&dA[r * LDSU + lcu], g_xn16 + ((size_t)(bm + r) * 4 + c) * DH + k0 + lch);
            }
            #pragma unroll
            for (int it = 0; it < 2; it++) {
                int r = lrow + it * 32;
                cp16(&dG[r * LDSU + lcu], wg0 + (size_t)(bn + r) * DH + k0 + lch);
                cp16(&dV[r * LDSU + lcu], wv0 + (size_t)(bn + r) * DH + k0 + lch);
            }
        }
        cp_commit();

        unsigned aBase = aLane + 4u * (unsigned)(slot * 128 * LDSU);
        unsigned gBase = gLane + 4u * (unsigned)(slot * 64 * LDSU);
        unsigned vBase = vLane + 4u * (unsigned)(slot * 64 * LDSU);
        #pragma unroll
        for (int kk = 0; kk < 32; kk += 8) {
            unsigned afr[2][4], g4[2][4], v4[2][4];
            #pragma unroll
            for (int mt = 0; mt < 2; mt++)
                ldsm4(afr[mt], aBase + 4u * (unsigned)(mt * 16 * LDSU + kk));
            #pragma unroll
            for (int p = 0; p < 2; p++) {
                ldsm4(g4[p], gBase + 4u * (unsigned)(p * 16 * LDSU + kk));
                ldsm4(v4[p], vBase + 4u * (unsigned)(p * 16 * LDSU + kk));
            }
            #pragma unroll
            for (int mt = 0; mt < 2; mt++)
                #pragma unroll
                for (int nt = 0; nt < 4; nt++) {
                    mma_f16(accg[mt][nt], afr[mt], &g4[nt >> 1][(nt & 1) * 2]);
                    mma_f16(accv[mt][nt], afr[mt], &v4[nt >> 1][(nt & 1) * 2]);
                }
        }
        slot = (slot == 2) ? 0 : slot + 1;
        nslot = (nslot == 2) ? 0 : nslot + 1;
    }

    #pragma unroll
    for (int mt = 0; mt < 2; mt++) {
        #pragma unroll
        for (int nt = 0; nt < 4; nt++) {
            int row0 = bm + wm + mt * 16 + g;
            int col  = bn + wn + nt * 8 + t * 2;
            #pragma unroll
            for (int half = 0; half < 2; half++) {
                int rr = row0 + half * 8;
                float gte0 = accg[mt][nt][half * 2 + 0];
                float gte1 = accg[mt][nt][half * 2 + 1];
                float val0 = accv[mt][nt][half * 2 + 0];
                float val1 = accv[mt][nt][half * 2 + 1];
                float h0 = gte0 / (1.f + expf(-gte0)) * val0;
                float h1 = gte1 / (1.f + expf(-gte1)) * val1;
                __half2* dst = (__half2*)(g_h16 + ((size_t)rr * 4 + c) * DH + col);
                *dst = __floats2half2_rn(h0, h1);
            }
        }
    }
}

// =====================================================================
// Stage 4 (FUSED): per-camera A = h16 @ wo16^T, then skew + clip + expm
// in-CTA via smem staging; writes out[C,B,6,6] directly.
// =====================================================================
__global__ __launch_bounds__(256, 2) void gemm3_kernel(float* __restrict__ out)
{
    extern __shared__ __align__(16) unsigned smb3[];
    unsigned* As = smb3;                     // [2][128*LDSU]
    unsigned* Bs = smb3 + 2 * 128 * LDSU;    // [2][40*LDSU]

    int tid  = threadIdx.x;
    int bm   = blockIdx.y * 128;
    int c    = blockIdx.z;
    int warp = tid >> 5, lane = tid & 31;
    int wm   = warp * 16;
    int g = lane >> 2, t = lane & 3;

    for (int i = tid; i < 2 * 4 * LDSU; i += 256) {
        int b = i / (4 * LDSU);
        int rem = i % (4 * LDSU);
        Bs[b * 40 * LDSU + 36 * LDSU + rem] = 0u;
    }

    float acc[5][4];
    #pragma unroll
    for (int j = 0; j < 5; j++)
        #pragma unroll
        for (int k = 0; k < 4; k++) acc[j][k] = 0.f;

    int lrow = tid >> 3;
    int lcu  = (tid & 7) * 4;
    int lch  = (tid & 7) * 8;
    const __half* wo0 = g_wo16 + (size_t)c * 36 * DH;
    const int NK = DH / 64;   // 8

    const unsigned sAs = (unsigned)__cvta_generic_to_shared(As);
    const unsigned sBs = (unsigned)__cvta_generic_to_shared(Bs);
    const unsigned aLane  = sAs + 4u * (unsigned)(wm * LDSU + A_LANE_OFF(lane));
    const unsigned bLane  = sBs + 4u * (unsigned)(B_LANE_OFF(lane));
    const unsigned b2Lane = sBs + 4u * (unsigned)(32 * LDSU + B2_LANE_OFF(lane));

    {
        #pragma unroll
        for (int it = 0; it < 4; it++) {
            int r = lrow + it * 32;
            cp16(&As[r * LDSU + lcu], g_h16 + ((size_t)(bm + r) * 4 + c) * DH + lch);
        }
        for (int i2 = tid; i2 < 288; i2 += 256) {
            int r = i2 >> 3, cu = (i2 & 7) * 4;
            cp16(&Bs[r * LDSU + cu], wo0 + (size_t)r * DH + (i2 & 7) * 8);
        }
        cp_commit();
    }

    for (int i = 0; i < NK; i++) {
        if (i + 1 < NK) {
            int k0 = (i + 1) * 64;
            int b = (i + 1) & 1;
            unsigned* dA = As + b * 128 * LDSU;
            unsigned* dB = Bs + b * 40 * LDSU;
            #pragma unroll
            for (int it = 0; it < 4; it++) {
                int r = lrow + it * 32;
                cp16(&dA[r * LDSU + lcu], g_h16 + ((size_t)(bm + r) * 4 + c) * DH + k0 + lch);
            }
            for (int i2 = tid; i2 < 288; i2 += 256) {
                int r = i2 >> 3, cu = (i2 & 7) * 4;
                cp16(&dB[r * LDSU + cu], wo0 + (size_t)r * DH + k0 + (i2 & 7) * 8);
            }
            cp_commit(); cp_wait1();
        } else {
            cp_wait0();
        }
        __syncthreads();

        int b = i & 1;
        unsigned aBase = aLane  + 4u * (unsigned)(b * 128 * LDSU);
        unsigned bBase = bLane  + 4u * (unsigned)(b * 40 * LDSU);
        unsigned cBase = b2Lane + 4u * (unsigned)(b * 40 * LDSU);
        #pragma unroll
        for (int kk = 0; kk < 32; kk += 8) {
            unsigned afr[4], b4[2][4], b2[2];
            ldsm4(afr, aBase + 4u * (unsigned)kk);
            #pragma unroll
            for (int p = 0; p < 2; p++)
                ldsm4(b4[p], bBase + 4u * (unsigned)(p * 16 * LDSU + kk));
            ldsm2(b2, cBase + 4u * (unsigned)kk);
            #pragma unroll
            for (int nt = 0; nt < 4; nt++)
                mma_f16(acc[nt], afr, &b4[nt >> 1][(nt & 1) * 2]);
            mma_f16(acc[4], afr, b2);
        }
        __syncthreads();
    }

    // ---- stage accumulators into smem (reuse pipeline buffers) ----
    float* stage = (float*)smb3;   // 128 x 37 floats = 18944 B
    #pragma unroll
    for (int nt = 0; nt < 5; nt++) {
        int col = nt * 8 + t * 2;
        if (col < 36) {
            int lr = wm + g;
            stage[lr * 37 + col]           = acc[nt][0];
            stage[lr * 37 + col + 1]       = acc[nt][1];
            stage[(lr + 8) * 37 + col]     = acc[nt][2];
            stage[(lr + 8) * 37 + col + 1] = acc[nt][3];
        }
    }
    __syncthreads();

    // ---- fused skew + clip + expm: one thread per matrix ----
    if (tid < 128) {
        const float* raw = stage + tid * 37;
        float A[36]; float ss = 0.f;
        #pragma unroll
        for (int i = 0; i < 6; i++)
            #pragma unroll
            for (int j = 0; j < 6; j++) {
                float v = raw[i * 6 + j] - raw[j * 6 + i];
                A[i * 6 + j] = v; ss += v * v;
            }
        float frob  = sqrtf(ss);
        float scale = fminf(frob, 3.0f) / fmaxf(frob, 1e-8f);

        float Asm[36];
        #pragma unroll
        for (int i = 0; i < 36; i++) Asm[i] = A[i] * scale * 0.0625f;

        float E[36], term[36];
        #pragma unroll
        for (int i = 0; i < 36; i++) { E[i] = (i % 7 == 0) ? 1.f : 0.f; term[i] = E[i]; }

        #pragma unroll 1
        for (int k = 1; k <= 12; k++) {
            float nt2[36];
            float inv = 1.f / (float)k;
            #pragma unroll
            for (int i = 0; i < 6; i++)
                #pragma unroll
                for (int j = 0; j < 6; j++) {
                    float sacc = 0.f;
                    #pragma unroll
                    for (int l = 0; l < 6; l++) sacc += term[i * 6 + l] * Asm[l * 6 + j];
                    nt2[i * 6 + j] = sacc * inv;
                }
            #pragma unroll
            for (int i = 0; i < 36; i++) { term[i] = nt2[i]; E[i] += nt2[i]; }
        }
        #pragma unroll 1
        for (int s = 0; s < 4; s++) {
            float nt2[36];
            #pragma unroll
            for (int i = 0; i < 6; i++)
                #pragma unroll
                for (int j = 0; j < 6; j++) {
                    float sacc = 0.f;
                    #pragma unroll
                    for (int l = 0; l < 6; l++) sacc += E[i * 6 + l] * E[l * 6 + j];
                    nt2[i * 6 + j] = sacc;
                }
            #pragma unroll
            for (int i = 0; i < 36; i++) E[i] = nt2[i];
        }

        float* dst = out + ((size_t)c * B_SZ + (bm + tid)) * 36;
        #pragma unroll
        for (int i = 0; i < 36; i++) dst[i] = E[i];
    }
}

// =====================================================================
extern "C" void kernel_launch(void* const* d_in, const int* in_sizes, int n_in,
                              void* d_out, int out_size)
{
    const float* thumb  = (const float*)d_in[0];
    const float* proj_w = (const float*)d_in[1];
    const float* proj_b = (const float*)d_in[2];
    const float* gamma  = (const float*)d_in[3];
    const float* beta   = (const float*)d_in[4];
    const float* w_gate = (const float*)d_in[5];
    const float* w_val  = (const float*)d_in[6];
    const float* w_out  = (const float*)d_in[7];
    float* out = (float*)d_out;

    (void)in_sizes; (void)n_in; (void)out_size;

    const int SM1 = 3 * 2 * 128 * LDSU * 4;                 // 110592
    const int SM2 = (3 * 128 * LDSU + 6 * 64 * LDSU) * 4;   // 110592
    const int SM3 = (2 * 128 * LDSU + 2 * 40 * LDSU) * 4;   // 48384

    cudaFuncSetAttribute(gemm1_kernel, cudaFuncAttributeMaxDynamicSharedMemorySize, SM1);
    cudaFuncSetAttribute(gemm2_kernel, cudaFuncAttributeMaxDynamicSharedMemorySize, SM2);
    cudaFuncSetAttribute(gemm3_kernel, cudaFuncAttributeMaxDynamicSharedMemorySize, SM3);

    conv_all<<<37152, 256>>>(thumb, proj_w, w_gate, w_val, w_out);
    gemm1_kernel<<<dim3(4, 512), 256, SM1>>>(proj_b);
    ln_kernel<<<MTOT / 8, 256>>>(gamma, beta);
    gemm2_kernel<<<dim3(8, 128, 4), 256, SM2>>>();
    gemm3_kernel<<<dim3(1, 128, 4), 256, SM3>>>(out);
}

// round 17
// speedup vs baseline: 1.4815x; 1.0018x over previous
#include <cuda_runtime.h>
#include <cuda_fp16.h>
#include <math.h>
#include <stdint.h>

#define B_SZ   16384
#define C_CAM  4
#define DBB    2048
#define DH     512
#define MTOT   (B_SZ * C_CAM)

// -------- device-global scratch (no allocations allowed) --------
__device__ __half g_reg16[(size_t)MTOT * DH];
__device__ __half g_t16 [(size_t)MTOT * DBB];
__device__ __half g_xn16[(size_t)MTOT * DH];
__device__ __half g_h16 [(size_t)MTOT * DH];
__device__ __half g_pw16[(size_t)DH * DBB];
__device__ __half g_wg16[(size_t)C_CAM * DH * DH];
__device__ __half g_wv16[(size_t)C_CAM * DH * DH];
__device__ __half g_wo16[(size_t)C_CAM * 36 * DH];

// -------- helpers --------
__device__ __forceinline__ void mma_f16(float d[4], const unsigned a[4], const unsigned b[2]) {
    asm volatile(
        "mma.sync.aligned.m16n8k16.row.col.f32.f16.f16.f32 "
        "{%0,%1,%2,%3}, {%4,%5,%6,%7}, {%8,%9}, {%0,%1,%2,%3};\n"
        : "+f"(d[0]), "+f"(d[1]), "+f"(d[2]), "+f"(d[3])
        : "r"(a[0]), "r"(a[1]), "r"(a[2]), "r"(a[3]), "r"(b[0]), "r"(b[1]));
}
__device__ __forceinline__ void ldsm4(unsigned r[4], unsigned saddr) {
    asm volatile("ldmatrix.sync.aligned.m8n8.x4.shared.b16 {%0,%1,%2,%3}, [%4];"
        : "=r"(r[0]), "=r"(r[1]), "=r"(r[2]), "=r"(r[3]) : "r"(saddr));
}
__device__ __forceinline__ void ldsm2(unsigned r[2], unsigned saddr) {
    asm volatile("ldmatrix.sync.aligned.m8n8.x2.shared.b16 {%0,%1}, [%2];"
        : "=r"(r[0]), "=r"(r[1]) : "r"(saddr));
}
__device__ __forceinline__ void cp16(void* s, const void* g) {
    unsigned a = (unsigned)__cvta_generic_to_shared(s);
    asm volatile("cp.async.cg.shared.global [%0], [%1], 16;\n" :: "r"(a), "l"(g));
}
__device__ __forceinline__ void cp_commit() { asm volatile("cp.async.commit_group;\n" ::: "memory"); }
__device__ __forceinline__ void cp_wait1()  { asm volatile("cp.async.wait_group 1;\n" ::: "memory"); }
__device__ __forceinline__ void cp_wait0()  { asm volatile("cp.async.wait_group 0;\n" ::: "memory"); }

#define LDSU 36   // uints per smem row: 32 data (=64 halves) + 4 pad

// lane-address offsets (uint units) for ldmatrix fragments
#define A_LANE_OFF(lane) (((lane) & 15) * LDSU + (((lane) >> 4) << 2))
#define B_LANE_OFF(lane) ((((lane) & 7) + (((lane) >> 4) << 3)) * LDSU + ((((lane) >> 3) & 1) << 2))
#define B2_LANE_OFF(lane) (((lane) & 7) * LDSU + ((((lane) >> 3) & 1) << 2))

// =====================================================================
// Stage 0 (fused): thumbnails (16 elem/thread) + all weights fp32->fp16
// blocks [0, 32768): thumbnails; [32768, 36864): pw/wg/wv; [36864, 37152): wo
// =====================================================================
__global__ __launch_bounds__(256) void conv_all(
    const float* __restrict__ T,  const float* __restrict__ pw,
    const float* __restrict__ wg, const float* __restrict__ wv,
    const float* __restrict__ wo)
{
    int bi = blockIdx.x;
    if (bi < 32768) {
        size_t t = (size_t)bi * 256 + threadIdx.x;
        const float4* s4 = (const float4*)T;
        uint4* d4 = (uint4*)g_t16;
        #pragma unroll
        for (int h = 0; h < 2; h++) {
            float4 a = s4[4 * t + 2 * h], b = s4[4 * t + 2 * h + 1];
            __half2 h0 = __floats2half2_rn(a.x, a.y);
            __half2 h1 = __floats2half2_rn(a.z, a.w);
            __half2 h2 = __floats2half2_rn(b.x, b.y);
            __half2 h3 = __floats2half2_rn(b.z, b.w);
            uint4 o;
            o.x = *(unsigned*)&h0; o.y = *(unsigned*)&h1;
            o.z = *(unsigned*)&h2; o.w = *(unsigned*)&h3;
            d4[2 * t + h] = o;
        }
    } else if (bi < 36864) {
        int i = (bi - 32768) * 256 + threadIdx.x;
        g_pw16[i] = __float2half_rn(pw[i]);
        g_wg16[i] = __float2half_rn(wg[i]);
        g_wv16[i] = __float2half_rn(wv[i]);
    } else {
        int i = (bi - 36864) * 256 + threadIdx.x;
        g_wo16[i] = __float2half_rn(wo[i]);
    }
}

// =====================================================================
// Stage 1: reg16 = t16 @ pw16^T + bias.  BM=128, BN=128, BK=64h.
// 3-stage cp.async, 1 barrier/tile, ldmatrix. 256 threads, 2 CTAs/SM.
// Output stored as fp16 (half2).
// =====================================================================
__global__ __launch_bounds__(256, 2) void gemm1_kernel(const float* __restrict__ bias)
{
    extern __shared__ __align__(16) unsigned smb1[];
    unsigned* As = smb1;                    // [3][128*LDSU]
    unsigned* Bs = smb1 + 3 * 128 * LDSU;   // [3][128*LDSU]

    int tid  = threadIdx.x;
    int bm   = blockIdx.y * 128;
    int bn   = blockIdx.x * 128;
    int warp = tid >> 5, lane = tid & 31;
    int wr = warp >> 2, wc = warp & 3;
    int wm = wr * 64,  wn = wc * 32;
    int g = lane >> 2, t = lane & 3;

    float acc[4][4][4];
    #pragma unroll
    for (int i = 0; i < 4; i++)
        #pragma unroll
        for (int j = 0; j < 4; j++)
            #pragma unroll
            for (int k = 0; k < 4; k++) acc[i][j][k] = 0.f;

    int lrow = tid >> 3;
    int lcu  = (tid & 7) * 4;
    int lch  = (tid & 7) * 8;
    const int NK = DBB / 64;        // 32

    const unsigned sAs = (unsigned)__cvta_generic_to_shared(As);
    const unsigned sBs = (unsigned)__cvta_generic_to_shared(Bs);
    const unsigned aLane = sAs + 4u * (unsigned)(wm * LDSU + A_LANE_OFF(lane));
    const unsigned bLane = sBs + 4u * (unsigned)(wn * LDSU + B_LANE_OFF(lane));

    #pragma unroll
    for (int s = 0; s < 2; s++) {
        unsigned* dA = As + s * 128 * LDSU;
        unsigned* dB = Bs + s * 128 * LDSU;
        int k0 = s * 64;
        #pragma unroll
        for (int it = 0; it < 4; it++) {
            int r = lrow + it * 32;
            cp16(&dA[r * LDSU + lcu], g_t16  + (size_t)(bm + r) * DBB + k0 + lch);
            cp16(&dB[r * LDSU + lcu], g_pw16 + (size_t)(bn + r) * DBB + k0 + lch);
        }
        cp_commit();
    }

    int slot = 0, nslot = 2;
    for (int i = 0; i < NK; i++) {
        cp_wait1();
        __syncthreads();

        if (i + 2 < NK) {
            int k0 = (i + 2) * 64;
            unsigned* dA = As + nslot * 128 * LDSU;
            unsigned* dB = Bs + nslot * 128 * LDSU;
            #pragma unroll
            for (int it = 0; it < 4; it++) {
                int r = lrow + it * 32;
                cp16(&dA[r * LDSU + lcu], g_t16  + (size_t)(bm + r) * DBB + k0 + lch);
                cp16(&dB[r * LDSU + lcu], g_pw16 + (size_t)(bn + r) * DBB + k0 + lch);
            }
        }
        cp_commit();

        unsigned aBase = aLane + 4u * (unsigned)(slot * 128 * LDSU);
        unsigned bBase = bLane + 4u * (unsigned)(slot * 128 * LDSU);
        #pragma unroll
        for (int kk = 0; kk < 32; kk += 8) {
            unsigned afr[4][4], b4[2][4];
            #pragma unroll
            for (int mt = 0; mt < 4; mt++)
                ldsm4(afr[mt], aBase + 4u * (unsigned)(mt * 16 * LDSU + kk));
            #pragma unroll
            for (int p = 0; p < 2; p++)
                ldsm4(b4[p], bBase + 4u * (unsigned)(p * 16 * LDSU + kk));
            #pragma unroll
            for (int mt = 0; mt < 4; mt++)
                #pragma unroll
                for (int nt = 0; nt < 4; nt++)
                    mma_f16(acc[mt][nt], afr[mt], &b4[nt >> 1][(nt & 1) * 2]);
        }
        slot = (slot == 2) ? 0 : slot + 1;
        nslot = (nslot == 2) ? 0 : nslot + 1;
    }

    #pragma unroll
    for (int mt = 0; mt < 4; mt++) {
        #pragma unroll
        for (int nt = 0; nt < 4; nt++) {
            int row0 = bm + wm + mt * 16 + g;
            int col  = bn + wn + nt * 8 + t * 2;
            float b0 = bias[col], b1 = bias[col + 1];
            *(__half2*)(g_reg16 + (size_t)row0 * DH + col) =
                __floats2half2_rn(acc[mt][nt][0] + b0, acc[mt][nt][1] + b1);
            *(__half2*)(g_reg16 + (size_t)(row0 + 8) * DH + col) =
                __floats2half2_rn(acc[mt][nt][2] + b0, acc[mt][nt][3] + b1);
        }
    }
}

// =====================================================================
// Stage 2: LayerNorm (warp/row) on fp16 input, fp16 output
// =====================================================================
__global__ __launch_bounds__(256) void ln_kernel(
    const float* __restrict__ gamma, const float* __restrict__ beta)
{
    int wglob = (blockIdx.x * blockDim.x + threadIdx.x) >> 5;
    int lane  = threadIdx.x & 31;
    if (wglob >= MTOT) return;
    int c = wglob & 3;
    const __half2* row2 = (const __half2*)(g_reg16 + (size_t)wglob * DH);
    float2 v[8]; float s = 0.f, s2 = 0.f;
    #pragma unroll
    for (int i = 0; i < 8; i++) {
        v[i] = __half22float2(row2[lane + i * 32]);
        s += v[i].x + v[i].y;
        s2 += v[i].x * v[i].x + v[i].y * v[i].y;
    }
    #pragma unroll
    for (int o = 16; o > 0; o >>= 1) {
        s  += __shfl_xor_sync(0xffffffffu, s,  o);
        s2 += __shfl_xor_sync(0xffffffffu, s2, o);
    }
    float mu   = s * (1.f / DH);
    float var  = s2 * (1.f / DH) - mu * mu;
    float rstd = rsqrtf(var + 1e-5f);
    __half2* orow = (__half2*)(g_xn16 + (size_t)wglob * DH);
    const float2* ga2 = (const float2*)(gamma + c * DH);
    const float2* be2 = (const float2*)(beta  + c * DH);
    #pragma unroll
    for (int i = 0; i < 8; i++) {
        int idx = lane + i * 32;
        float2 ga = ga2[idx], be = be2[idx];
        float x0 = (v[i].x - mu) * rstd * ga.x + be.x;
        float x1 = (v[i].y - mu) * rstd * ga.y + be.y;
        orow[idx] = __floats2half2_rn(x0, x1);
    }
}

// =====================================================================
// Stage 3: per-camera dual GEMM + SwiGLU. BM=128, BN=64, BK=64h. NK=8.
// 3-stage, 1 barrier/tile, ldmatrix loads.
// =====================================================================
__global__ __launch_bounds__(256, 2) void gemm2_kernel()
{
    extern __shared__ __align__(16) unsigned smb2[];
    unsigned* As  = smb2;                       // [3][128*LDSU]
    unsigned* Bgs = smb2 + 3 * 128 * LDSU;      // [3][64*LDSU]
    unsigned* Bvs = Bgs + 3 * 64 * LDSU;        // [3][64*LDSU]

    int tid  = threadIdx.x;
    int bm   = blockIdx.y * 128;
    int bn   = blockIdx.x * 64;
    int c    = blockIdx.z;
    int warp = tid >> 5, lane = tid & 31;
    int wr = warp >> 1, wc = warp & 1;
    int wm = wr * 32,  wn = wc * 32;
    int g = lane >> 2, t = lane & 3;

    float accg[2][4][4], accv[2][4][4];
    #pragma unroll
    for (int i = 0; i < 2; i++)
        #pragma unroll
        for (int j = 0; j < 4; j++)
            #pragma unroll
            for (int k = 0; k < 4; k++) { accg[i][j][k] = 0.f; accv[i][j][k] = 0.f; }

    int lrow = tid >> 3;
    int lcu  = (tid & 7) * 4;
    int lch  = (tid & 7) * 8;
    const __half* wg0 = g_wg16 + (size_t)c * DH * DH;
    const __half* wv0 = g_wv16 + (size_t)c * DH * DH;
    const int NK = DH / 64;   // 8

    const unsigned sAs = (unsigned)__cvta_generic_to_shared(As);
    const unsigned sGs = (unsigned)__cvta_generic_to_shared(Bgs);
    const unsigned sVs = (unsigned)__cvta_generic_to_shared(Bvs);
    const unsigned aLane = sAs + 4u * (unsigned)(wm * LDSU + A_LANE_OFF(lane));
    const unsigned gLane = sGs + 4u * (unsigned)(wn * LDSU + B_LANE_OFF(lane));
    const unsigned vLane = sVs + 4u * (unsigned)(wn * LDSU + B_LANE_OFF(lane));

    #pragma unroll
    for (int s = 0; s < 2; s++) {
        int k0 = s * 64;
        unsigned* dA = As  + s * 128 * LDSU;
        unsigned* dG = Bgs + s * 64 * LDSU;
        unsigned* dV = Bvs + s * 64 * LDSU;
        #pragma unroll
        for (int it = 0; it < 4; it++) {
            int r = lrow + it * 32;
            cp16(&dA[r * LDSU + lcu], g_xn16 + ((size_t)(bm + r) * 4 + c) * DH + k0 + lch);
        }
        #pragma unroll
        for (int it = 0; it < 2; it++) {
            int r = lrow + it * 32;
            cp16(&dG[r * LDSU + lcu], wg0 + (size_t)(bn + r) * DH + k0 + lch);
            cp16(&dV[r * LDSU + lcu], wv0 + (size_t)(bn + r) * DH + k0 + lch);
        }
        cp_commit();
    }

    int slot = 0, nslot = 2;
    for (int i = 0; i < NK; i++) {
        cp_wait1();
        __syncthreads();

        if (i + 2 < NK) {
            int k0 = (i + 2) * 64;
            unsigned* dA = As  + nslot * 128 * LDSU;
            unsigned* dG = Bgs + nslot * 64 * LDSU;
            unsigned* dV = Bvs + nslot * 64 * LDSU;
            #pragma unroll
            for (int it = 0; it < 4; it++) {
                int r = lrow + it * 32;
                cp16(&dA[r * LDSU + lcu], g_xn16 + ((size_t)(bm + r) * 4 + c) * DH + k0 + lch);
            }
            #pragma unroll
            for (int it = 0; it < 2; it++) {
                int r = lrow + it * 32;
                cp16(&dG[r * LDSU + lcu], wg0 + (size_t)(bn + r) * DH + k0 + lch);
                cp16(&dV[r * LDSU + lcu], wv0 + (size_t)(bn + r) * DH + k0 + lch);
            }
        }
        cp_commit();

        unsigned aBase = aLane + 4u * (unsigned)(slot * 128 * LDSU);
        unsigned gBase = gLane + 4u * (unsigned)(slot * 64 * LDSU);
        unsigned vBase = vLane + 4u * (unsigned)(slot * 64 * LDSU);
        #pragma unroll
        for (int kk = 0; kk < 32; kk += 8) {
            unsigned afr[2][4], g4[2][4], v4[2][4];
            #pragma unroll
            for (int mt = 0; mt < 2; mt++)
                ldsm4(afr[mt], aBase + 4u * (unsigned)(mt * 16 * LDSU + kk));
            #pragma unroll
            for (int p = 0; p < 2; p++) {
                ldsm4(g4[p], gBase + 4u * (unsigned)(p * 16 * LDSU + kk));
                ldsm4(v4[p], vBase + 4u * (unsigned)(p * 16 * LDSU + kk));
            }
            #pragma unroll
            for (int mt = 0; mt < 2; mt++)
                #pragma unroll
                for (int nt = 0; nt < 4; nt++) {
                    mma_f16(accg[mt][nt], afr[mt], &g4[nt >> 1][(nt & 1) * 2]);
                    mma_f16(accv[mt][nt], afr[mt], &v4[nt >> 1][(nt & 1) * 2]);
                }
        }
        slot = (slot == 2) ? 0 : slot + 1;
        nslot = (nslot == 2) ? 0 : nslot + 1;
    }

    #pragma unroll
    for (int mt = 0; mt < 2; mt++) {
        #pragma unroll
        for (int nt = 0; nt < 4; nt++) {
            int row0 = bm + wm + mt * 16 + g;
            int col  = bn + wn + nt * 8 + t * 2;
            #pragma unroll
            for (int half = 0; half < 2; half++) {
                int rr = row0 + half * 8;
                float gte0 = accg[mt][nt][half * 2 + 0];
                float gte1 = accg[mt][nt][half * 2 + 1];
                float val0 = accv[mt][nt][half * 2 + 0];
                float val1 = accv[mt][nt][half * 2 + 1];
                float h0 = gte0 / (1.f + expf(-gte0)) * val0;
                float h1 = gte1 / (1.f + expf(-gte1)) * val1;
                __half2* dst = (__half2*)(g_h16 + ((size_t)rr * 4 + c) * DH + col);
                *dst = __floats2half2_rn(h0, h1);
            }
        }
    }
}

// =====================================================================
// Stage 4 (FUSED): per-camera A = h16 @ wo16^T, then skew + clip + expm
// in-CTA via smem staging; writes out[C,B,6,6] directly.
// =====================================================================
__global__ __launch_bounds__(256, 2) void gemm3_kernel(float* __restrict__ out)
{
    extern __shared__ __align__(16) unsigned smb3[];
    unsigned* As = smb3;                     // [2][128*LDSU]
    unsigned* Bs = smb3 + 2 * 128 * LDSU;    // [2][40*LDSU]

    int tid  = threadIdx.x;
    int bm   = blockIdx.y * 128;
    int c    = blockIdx.z;
    int warp = tid >> 5, lane = tid & 31;
    int wm   = warp * 16;
    int g = lane >> 2, t = lane & 3;

    for (int i = tid; i < 2 * 4 * LDSU; i += 256) {
        int b = i / (4 * LDSU);
        int rem = i % (4 * LDSU);
        Bs[b * 40 * LDSU + 36 * LDSU + rem] = 0u;
    }

    float acc[5][4];
    #pragma unroll
    for (int j = 0; j < 5; j++)
        #pragma unroll
        for (int k = 0; k < 4; k++) acc[j][k] = 0.f;

    int lrow = tid >> 3;
    int lcu  = (tid & 7) * 4;
    int lch  = (tid & 7) * 8;
    const __half* wo0 = g_wo16 + (size_t)c * 36 * DH;
    const int NK = DH / 64;   // 8

    const unsigned sAs = (unsigned)__cvta_generic_to_shared(As);
    const unsigned sBs = (unsigned)__cvta_generic_to_shared(Bs);
    const unsigned aLane  = sAs + 4u * (unsigned)(wm * LDSU + A_LANE_OFF(lane));
    const unsigned bLane  = sBs + 4u * (unsigned)(B_LANE_OFF(lane));
    const unsigned b2Lane = sBs + 4u * (unsigned)(32 * LDSU + B2_LANE_OFF(lane));

    {
        #pragma unroll
        for (int it = 0; it < 4; it++) {
            int r = lrow + it * 32;
            cp16(&As[r * LDSU + lcu], g_h16 + ((size_t)(bm + r) * 4 + c) * DH + lch);
        }
        for (int i2 = tid; i2 < 288; i2 += 256) {
            int r = i2 >> 3, cu = (i2 & 7) * 4;
            cp16(&Bs[r * LDSU + cu], wo0 + (size_t)r * DH + (i2 & 7) * 8);
        }
        cp_commit();
    }

    for (int i = 0; i < NK; i++) {
        if (i + 1 < NK) {
            int k0 = (i + 1) * 64;
            int b = (i + 1) & 1;
            unsigned* dA = As + b * 128 * LDSU;
            unsigned* dB = Bs + b * 40 * LDSU;
            #pragma unroll
            for (int it = 0; it < 4; it++) {
                int r = lrow + it * 32;
                cp16(&dA[r * LDSU + lcu], g_h16 + ((size_t)(bm + r) * 4 + c) * DH + k0 + lch);
            }
            for (int i2 = tid; i2 < 288; i2 += 256) {
                int r = i2 >> 3, cu = (i2 & 7) * 4;
                cp16(&dB[r * LDSU + cu], wo0 + (size_t)r * DH + k0 + (i2 & 7) * 8);
            }
            cp_commit(); cp_wait1();
        } else {
            cp_wait0();
        }
        __syncthreads();

        int b = i & 1;
        unsigned aBase = aLane  + 4u * (unsigned)(b * 128 * LDSU);
        unsigned bBase = bLane  + 4u * (unsigned)(b * 40 * LDSU);
        unsigned cBase = b2Lane + 4u * (unsigned)(b * 40 * LDSU);
        #pragma unroll
        for (int kk = 0; kk < 32; kk += 8) {
            unsigned afr[4], b4[2][4], b2[2];
            ldsm4(afr, aBase + 4u * (unsigned)kk);
            #pragma unroll
            for (int p = 0; p < 2; p++)
                ldsm4(b4[p], bBase + 4u * (unsigned)(p * 16 * LDSU + kk));
            ldsm2(b2, cBase + 4u * (unsigned)kk);
            #pragma unroll
            for (int nt = 0; nt < 4; nt++)
                mma_f16(acc[nt], afr, &b4[nt >> 1][(nt & 1) * 2]);
            mma_f16(acc[4], afr, b2);
        }
        __syncthreads();
    }

    // ---- stage accumulators into smem (reuse pipeline buffers) ----
    float* stage = (float*)smb3;   // 128 x 37 floats = 18944 B
    #pragma unroll
    for (int nt = 0; nt < 5; nt++) {
        int col = nt * 8 + t * 2;
        if (col < 36) {
            int lr = wm + g;
            stage[lr * 37 + col]           = acc[nt][0];
            stage[lr * 37 + col + 1]       = acc[nt][1];
            stage[(lr + 8) * 37 + col]     = acc[nt][2];
            stage[(lr + 8) * 37 + col + 1] = acc[nt][3];
        }
    }
    __syncthreads();

    // ---- fused skew + clip + expm: one thread per matrix ----
    if (tid < 128) {
        const float* raw = stage + tid * 37;
        float A[36]; float ss = 0.f;
        #pragma unroll
        for (int i = 0; i < 6; i++)
            #pragma unroll
            for (int j = 0; j < 6; j++) {
                float v = raw[i * 6 + j] - raw[j * 6 + i];
                A[i * 6 + j] = v; ss += v * v;
            }
        float frob  = sqrtf(ss);
        float scale = fminf(frob, 3.0f) / fmaxf(frob, 1e-8f);

        float Asm[36];
        #pragma unroll
        for (int i = 0; i < 36; i++) Asm[i] = A[i] * scale * 0.0625f;

        float E[36], term[36];
        #pragma unroll
        for (int i = 0; i < 36; i++) { E[i] = (i % 7 == 0) ? 1.f : 0.f; term[i] = E[i]; }

        #pragma unroll 1
        for (int k = 1; k <= 12; k++) {
            float nt2[36];
            float inv = 1.f / (float)k;
            #pragma unroll
            for (int i = 0; i < 6; i++)
                #pragma unroll
                for (int j = 0; j < 6; j++) {
                    float sacc = 0.f;
                    #pragma unroll
                    for (int l = 0; l < 6; l++) sacc += term[i * 6 + l] * Asm[l * 6 + j];
                    nt2[i * 6 + j] = sacc * inv;
                }
            #pragma unroll
            for (int i = 0; i < 36; i++) { term[i] = nt2[i]; E[i] += nt2[i]; }
        }
        #pragma unroll 1
        for (int s = 0; s < 4; s++) {
            float nt2[36];
            #pragma unroll
            for (int i = 0; i < 6; i++)
                #pragma unroll
                for (int j = 0; j < 6; j++) {
                    float sacc = 0.f;
                    #pragma unroll
                    for (int l = 0; l < 6; l++) sacc += E[i * 6 + l] * E[l * 6 + j];
                    nt2[i * 6 + j] = sacc;
                }
            #pragma unroll
            for (int i = 0; i < 36; i++) E[i] = nt2[i];
        }

        float* dst = out + ((size_t)c * B_SZ + (bm + tid)) * 36;
        #pragma unroll
        for (int i = 0; i < 36; i++) dst[i] = E[i];
    }
}

// =====================================================================
extern "C" void kernel_launch(void* const* d_in, const int* in_sizes, int n_in,
                              void* d_out, int out_size)
{
    const float* thumb  = (const float*)d_in[0];
    const float* proj_w = (const float*)d_in[1];
    const float* proj_b = (const float*)d_in[2];
    const float* gamma  = (const float*)d_in[3];
    const float* beta   = (const float*)d_in[4];
    const float* w_gate = (const float*)d_in[5];
    const float* w_val  = (const float*)d_in[6];
    const float* w_out  = (const float*)d_in[7];
    float* out = (float*)d_out;

    (void)in_sizes; (void)n_in; (void)out_size;

    const int SM1 = 3 * 2 * 128 * LDSU * 4;                 // 110592
    const int SM2 = (3 * 128 * LDSU + 6 * 64 * LDSU) * 4;   // 110592
    const int SM3 = (2 * 128 * LDSU + 2 * 40 * LDSU) * 4;   // 48384

    cudaFuncSetAttribute(gemm1_kernel, cudaFuncAttributeMaxDynamicSharedMemorySize, SM1);
    cudaFuncSetAttribute(gemm2_kernel, cudaFuncAttributeMaxDynamicSharedMemorySize, SM2);
    cudaFuncSetAttribute(gemm3_kernel, cudaFuncAttributeMaxDynamicSharedMemorySize, SM3);

    conv_all<<<37152, 256>>>(thumb, proj_w, w_gate, w_val, w_out);
    gemm1_kernel<<<dim3(4, 512), 256, SM1>>>(proj_b);
    ln_kernel<<<MTOT / 8, 256>>>(gamma, beta);
    gemm2_kernel<<<dim3(8, 128, 4), 256, SM2>>>();
    gemm3_kernel<<<dim3(1, 128, 4), 256, SM3>>>(out);
}